// round 13
// baseline (speedup 1.0000x reference)
#include <cuda_runtime.h>
#include <cuda_bf16.h>
#include <cstdint>

// Problem constants (fixed by the reference)
#define NNODES 100000
#define FDIM   128
#define HID    128
#define NCLS   40
#define EMAX   1600000
#define NEG_SLOPE 0.2f
#define BN_EPS 1e-5f

#define SCAN_BLK 1024
#define NSCANBLK ((NNODES + SCAN_BLK - 1) / SCAN_BLK)   // 98

// ----------------------------------------------------------------------------
// Device scratch (static globals — no runtime allocation allowed)
// ----------------------------------------------------------------------------
__device__ float g_h[NNODES * HID];      // linear output of current layer
__device__ float g_out[NNODES * HID];    // GAT aggregation output (pre-BN)
__device__ float g_as[NNODES];
__device__ float g_ad[NNODES];
__device__ float g_se[EMAX];             // cached per-slot edge scores
__device__ float g_stats[2 * HID];       // per-channel sum / sumsq
__device__ float g_bnsc[HID];            // folded BN scale (gamma * rstd)
__device__ float g_bnsh[HID];            // folded BN shift (beta - mean*scale)

// Prepacked bf16{hi,lo} operands, kp-major (kp = k/2 pair index)
__device__ uint2 g_Ap[64 * NNODES + 128];   // [kp][m], padded for tile overrun
__device__ uint2 g_Bp[64 * 128];            // [kp][n]

// CSR (dst -> list of src), rebuilt every launch (deterministic)
__device__ int g_deg[NNODES];
__device__ int g_fill[NNODES];           // running fill cursor (seeded = rowptr)
__device__ int g_rowptr[NNODES + 1];
__device__ int g_blocksum[128];
__device__ int g_csrc[EMAX];

// ----------------------------------------------------------------------------
__device__ __forceinline__ float lrelu(float x) {
    return x > 0.f ? x : NEG_SLOPE * x;
}

__device__ __forceinline__ unsigned bfpack(float lo, float hi) {
    __nv_bfloat162 p = __floats2bfloat162_rn(lo, hi);
    return *(unsigned*)&p;
}

__device__ __forceinline__ uint2 split2(float va, float vb) {
    float a0 = __bfloat162float(__float2bfloat16_rn(va));
    float b0 = __bfloat162float(__float2bfloat16_rn(vb));
    return make_uint2(bfpack(a0, b0), bfpack(va - a0, vb - b0));
}

__device__ __forceinline__ void mma_bf16(float d[4], const unsigned a[4],
                                         const unsigned b[2], const float c[4]) {
    asm volatile(
        "mma.sync.aligned.m16n8k16.row.col.f32.bf16.bf16.f32 "
        "{%0,%1,%2,%3}, {%4,%5,%6,%7}, {%8,%9}, {%10,%11,%12,%13};"
        : "=f"(d[0]), "=f"(d[1]), "=f"(d[2]), "=f"(d[3])
        : "r"(a[0]), "r"(a[1]), "r"(a[2]), "r"(a[3]),
          "r"(b[0]), "r"(b[1]),
          "f"(c[0]), "f"(c[1]), "f"(c[2]), "f"(c[3]));
}

__device__ __forceinline__ uint32_t smem_u32(const void* p) {
    return (uint32_t)__cvta_generic_to_shared(p);
}

// ----------------------------------------------------------------------------
// Prepack A: [m][k] float -> [kp][m] uint2 bf16{hi,lo}. Optional BN+ReLU.
// ----------------------------------------------------------------------------
template<bool BNA>
__global__ void aprep_kernel(const float* __restrict__ A)
{
    __shared__ uint2 s[64][65];
    int m0 = blockIdx.x * 64;
    for (int i = threadIdx.x; i < 64 * 64; i += 256) {
        int r = i >> 6, kp = i & 63;
        float2 v = make_float2(0.f, 0.f);
        if (m0 + r < NNODES)
            v = *(const float2*)(A + (size_t)(m0 + r) * HID + 2 * kp);
        if (BNA) {
            int c = 2 * kp;
            v.x = fmaxf(v.x * g_bnsc[c] + g_bnsh[c], 0.f);
            v.y = fmaxf(v.y * g_bnsc[c + 1] + g_bnsh[c + 1], 0.f);
        }
        s[r][kp] = split2(v.x, v.y);
    }
    __syncthreads();
    for (int i = threadIdx.x; i < 64 * 64; i += 256) {
        int kp = i >> 6, r = i & 63;
        if (m0 + r < NNODES)
            g_Ap[(size_t)kp * NNODES + m0 + r] = s[r][kp];
    }
}

// ----------------------------------------------------------------------------
// Prepack B: [k][n] float -> [kp][n] uint2 bf16{hi,lo}, n padded.
// ----------------------------------------------------------------------------
__global__ void bprep_kernel(const float* __restrict__ B, int K, int NC, int NPAD)
{
    int i = blockIdx.x * blockDim.x + threadIdx.x;
    if (i >= (K / 2) * NPAD) return;
    int kp = i / NPAD, n = i % NPAD;
    float be = 0.f, bo = 0.f;
    if (n < NC) {
        be = B[(size_t)(2 * kp) * NC + n];
        bo = B[(size_t)(2 * kp + 1) * NC + n];
    }
    g_Bp[i] = split2(be, bo);
}

// ----------------------------------------------------------------------------
// bf16x3 GEMM, 3-stage cp.async pipeline, FULLY UNROLLED (K compile-time).
// Optional fused alpha-dot epilogue (DOTS) writes g_as/g_ad.
// ----------------------------------------------------------------------------
template<int BM, int BN, int NWM, int NWN, bool BIAS, bool NGUARD, bool DOTS, int K>
__global__ void __launch_bounds__(NWM * NWN * 32, 2)
mma_gemm_kernel(const uint2* __restrict__ Ap, const uint2* __restrict__ Bp,
                const float* __restrict__ bias,
                const float* __restrict__ avs, const float* __restrict__ avd,
                float* __restrict__ C, int M, int NC, int NPAD)
{
    constexpr int THREADS = NWM * NWN * 32;
    constexpr int WM = BM / NWM;
    constexpr int WN = BN / NWN;
    constexpr int MT = WM / 16;
    constexpr int NT = WN / 8;
    constexpr int PAD = 2;
    constexpr int NITER = K / 16;

    extern __shared__ __align__(16) char dyn[];
    uint2 (*As)[8][BM + PAD] = (uint2(*)[8][BM + PAD])dyn;
    uint2 (*Bs)[8][BN + PAD] =
        (uint2(*)[8][BN + PAD])(dyn + 3 * 8 * (BM + PAD) * sizeof(uint2));
    float* sdot = (float*)(dyn + 3 * 8 * (BM + PAD) * sizeof(uint2)
                               + 3 * 8 * (BN + PAD) * sizeof(uint2));

    const int tid    = threadIdx.x;
    const int warpId = tid >> 5;
    const int lane   = tid & 31;
    const int warpM  = warpId % NWM;
    const int warpN  = warpId / NWM;
    const int t      = lane & 3;
    const int g      = lane >> 2;
    const int rowBase = blockIdx.x * BM;

#define ISSUE_STAGE(st, buf) do {                                              \
    int kpb = (st) * 8;                                                        \
    _Pragma("unroll")                                                          \
    for (int u = tid; u < (BM * 8) / 2; u += THREADS) {                        \
        int kpl = u / (BM / 2); int mu = u % (BM / 2);                         \
        const void* gsrc = Ap + (size_t)(kpb + kpl) * M + rowBase + mu * 2;    \
        uint32_t d = smem_u32(&As[buf][kpl][mu * 2]);                          \
        asm volatile("cp.async.cg.shared.global [%0], [%1], 16;"               \
                     :: "r"(d), "l"(gsrc));                                    \
    }                                                                          \
    _Pragma("unroll")                                                          \
    for (int u = tid; u < (BN * 8) / 2; u += THREADS) {                        \
        int kpl = u / (BN / 2); int nu = u % (BN / 2);                         \
        const void* gsrc = Bp + (size_t)(kpb + kpl) * NPAD + nu * 2;           \
        uint32_t d = smem_u32(&Bs[buf][kpl][nu * 2]);                          \
        asm volatile("cp.async.cg.shared.global [%0], [%1], 16;"               \
                     :: "r"(d), "l"(gsrc));                                    \
    }                                                                          \
    asm volatile("cp.async.commit_group;");                                    \
} while (0)

    float acc[MT][NT][4];
#pragma unroll
    for (int i = 0; i < MT; i++)
#pragma unroll
        for (int j = 0; j < NT; j++)
#pragma unroll
            for (int r = 0; r < 4; r++) acc[i][j][r] = 0.f;

    ISSUE_STAGE(0, 0);
    ISSUE_STAGE(1, 1);

#pragma unroll
    for (int it = 0; it < NITER; ++it) {
        if (it + 1 < NITER)
            asm volatile("cp.async.wait_group 1;");
        else
            asm volatile("cp.async.wait_group 0;");
        __syncthreads();
        if (it + 2 < NITER) ISSUE_STAGE(it + 2, (it + 2) % 3);

        const int cur = it % 3;
        unsigned a0[MT][4], a1[MT][4];
#pragma unroll
        for (int mt = 0; mt < MT; mt++) {
            int mr = warpM * WM + mt * 16;
            uint2 v0 = As[cur][t][mr + g];
            uint2 v1 = As[cur][t][mr + g + 8];
            uint2 v2 = As[cur][t + 4][mr + g];
            uint2 v3 = As[cur][t + 4][mr + g + 8];
            a0[mt][0] = v0.x; a1[mt][0] = v0.y;
            a0[mt][1] = v1.x; a1[mt][1] = v1.y;
            a0[mt][2] = v2.x; a1[mt][2] = v2.y;
            a0[mt][3] = v3.x; a1[mt][3] = v3.y;
        }
        unsigned b0[NT][2], b1[NT][2];
#pragma unroll
        for (int nt = 0; nt < NT; nt++) {
            int nc0 = warpN * WN + nt * 8;
            uint2 w0 = Bs[cur][t][nc0 + g];
            uint2 w1 = Bs[cur][t + 4][nc0 + g];
            b0[nt][0] = w0.x; b1[nt][0] = w0.y;
            b0[nt][1] = w1.x; b1[nt][1] = w1.y;
        }
#pragma unroll
        for (int mt = 0; mt < MT; mt++)
#pragma unroll
            for (int nt = 0; nt < NT; nt++) {
                mma_bf16(acc[mt][nt], a0[mt], b1[nt], acc[mt][nt]);
                mma_bf16(acc[mt][nt], a1[mt], b0[nt], acc[mt][nt]);
                mma_bf16(acc[mt][nt], a0[mt], b0[nt], acc[mt][nt]);
            }
    }
#undef ISSUE_STAGE

    // ---- C store ----
#pragma unroll
    for (int mt = 0; mt < MT; mt++) {
#pragma unroll
        for (int nt = 0; nt < NT; nt++) {
            int col = warpN * WN + nt * 8 + 2 * t;
            if (NGUARD && col >= NC) continue;
            float b0v = 0.f, b1v = 0.f;
            if (BIAS) { b0v = bias[col]; b1v = bias[col + 1]; }
            int row0 = rowBase + warpM * WM + mt * 16 + g;
            if (row0 < M) {
                float2 v = make_float2(acc[mt][nt][0] + b0v, acc[mt][nt][1] + b1v);
                *(float2*)(C + (size_t)row0 * NC + col) = v;
            }
            int row1 = row0 + 8;
            if (row1 < M) {
                float2 v = make_float2(acc[mt][nt][2] + b0v, acc[mt][nt][3] + b1v);
                *(float2*)(C + (size_t)row1 * NC + col) = v;
            }
        }
    }

    // ---- Fused alpha-dot epilogue ----
    if (DOTS) {
        float psA[MT], pdA[MT], psB[MT], pdB[MT];
#pragma unroll
        for (int mt = 0; mt < MT; mt++) {
            psA[mt] = 0.f; pdA[mt] = 0.f; psB[mt] = 0.f; pdB[mt] = 0.f;
        }
#pragma unroll
        for (int nt = 0; nt < NT; nt++) {
            int col = warpN * WN + nt * 8 + 2 * t;
            float s0 = avs[col], s1 = avs[col + 1];
            float d0 = avd[col], d1 = avd[col + 1];
#pragma unroll
            for (int mt = 0; mt < MT; mt++) {
                psA[mt] += acc[mt][nt][0] * s0 + acc[mt][nt][1] * s1;
                pdA[mt] += acc[mt][nt][0] * d0 + acc[mt][nt][1] * d1;
                psB[mt] += acc[mt][nt][2] * s0 + acc[mt][nt][3] * s1;
                pdB[mt] += acc[mt][nt][2] * d0 + acc[mt][nt][3] * d1;
            }
        }
#pragma unroll
        for (int o = 1; o <= 2; o <<= 1) {
#pragma unroll
            for (int mt = 0; mt < MT; mt++) {
                psA[mt] += __shfl_xor_sync(0xffffffffu, psA[mt], o);
                pdA[mt] += __shfl_xor_sync(0xffffffffu, pdA[mt], o);
                psB[mt] += __shfl_xor_sync(0xffffffffu, psB[mt], o);
                pdB[mt] += __shfl_xor_sync(0xffffffffu, pdB[mt], o);
            }
        }
        if (t == 0) {
#pragma unroll
            for (int mt = 0; mt < MT; mt++) {
                int rA = warpM * WM + mt * 16 + g;
                sdot[(rA * NWN + warpN) * 2 + 0] = psA[mt];
                sdot[(rA * NWN + warpN) * 2 + 1] = pdA[mt];
                sdot[((rA + 8) * NWN + warpN) * 2 + 0] = psB[mt];
                sdot[((rA + 8) * NWN + warpN) * 2 + 1] = pdB[mt];
            }
        }
        __syncthreads();
        for (int r = tid; r < BM; r += THREADS) {
            int grow = rowBase + r;
            if (grow < M) {
                float ss = 0.f, dd = 0.f;
#pragma unroll
                for (int wn = 0; wn < NWN; wn++) {
                    ss += sdot[(r * NWN + wn) * 2 + 0];
                    dd += sdot[(r * NWN + wn) * 2 + 1];
                }
                g_as[grow] = ss;
                g_ad[grow] = dd;
            }
        }
    }
}

// ----------------------------------------------------------------------------
// CSR build kernels (edge indices are int32)
// ----------------------------------------------------------------------------
__global__ void csr_zero_kernel()
{
    int i = blockIdx.x * blockDim.x + threadIdx.x;
    if (i < NNODES) g_deg[i] = 0;
    if (i < 2 * HID) g_stats[i] = 0.f;
}

__global__ void csr_count_kernel(const int* __restrict__ dstp, int E)
{
    int e = blockIdx.x * blockDim.x + threadIdx.x;
    if (e < E) atomicAdd(&g_deg[dstp[e]], 1);
}

__global__ void csr_scan_block_kernel()
{
    __shared__ int s[SCAN_BLK];
    int t = threadIdx.x;
    int i = blockIdx.x * SCAN_BLK + t;
    int v = (i < NNODES) ? g_deg[i] : 0;
    s[t] = v;
    __syncthreads();
#pragma unroll
    for (int off = 1; off < SCAN_BLK; off <<= 1) {
        int x = (t >= off) ? s[t - off] : 0;
        __syncthreads();
        s[t] += x;
        __syncthreads();
    }
    if (i < NNODES) g_rowptr[i] = s[t] - v;       // exclusive within block
    if (t == SCAN_BLK - 1) g_blocksum[blockIdx.x] = s[t];
}

__global__ void csr_scan_tops_kernel(int nblocks, int E)
{
    __shared__ int s[128];
    int t = threadIdx.x;                            // 128 threads
    int v = (t < nblocks) ? g_blocksum[t] : 0;
    s[t] = v;
    __syncthreads();
#pragma unroll
    for (int off = 1; off < 128; off <<= 1) {
        int x = (t >= off) ? s[t - off] : 0;
        __syncthreads();
        s[t] += x;
        __syncthreads();
    }
    g_blocksum[t] = s[t] - v;                       // exclusive block offsets
    if (t == 0) g_rowptr[NNODES] = E;
}

__global__ void csr_addoff_kernel()
{
    int i = blockIdx.x * SCAN_BLK + threadIdx.x;
    if (i < NNODES) {
        int r = g_rowptr[i] + g_blocksum[blockIdx.x];
        g_rowptr[i] = r;
        g_fill[i] = r;                              // seed fill cursor
    }
}

__global__ void csr_fill_kernel(const int* __restrict__ srcp,
                                const int* __restrict__ dstp, int E)
{
    int e = blockIdx.x * blockDim.x + threadIdx.x;
    if (e >= E) return;
    int p = atomicAdd(&g_fill[dstp[e]], 1);
    g_csrc[p] = srcp[e];
}

// ----------------------------------------------------------------------------
// Fused segment softmax + aggregation + bias + BN-stats.
// One warp per destination node; scores cached in g_se (coalesced reuse).
// ----------------------------------------------------------------------------
__global__ void gat_node_kernel(const float* __restrict__ h,
                                const float* __restrict__ bias)
{
    __shared__ float red[8][HID];

    const int tid  = threadIdx.x;
    const int w    = tid >> 5;
    const int lane = tid & 31;
    const int n    = (blockIdx.x * blockDim.x + tid) >> 5;

    float4 outv = make_float4(0.f, 0.f, 0.f, 0.f);

    if (n < NNODES) {
        const int beg = g_rowptr[n];
        const int end = g_rowptr[n + 1];
        const float adn = g_ad[n];
        const float selfs = lrelu(g_as[n] + adn);

        // Pass 1: gather scores once, cache, segment max
        float m = selfs;
        for (int i = beg + lane; i < end; i += 32) {
            float s = lrelu(g_as[g_csrc[i]] + adn);
            g_se[i] = s;
            m = fmaxf(m, s);
        }
#pragma unroll
        for (int o = 16; o > 0; o >>= 1)
            m = fmaxf(m, __shfl_xor_sync(0xffffffffu, m, o));
        __syncwarp();

        // Pass 2: exp-sum (coalesced reads of cached scores)
        float sum = 0.f;
        for (int i = beg + lane; i < end; i += 32)
            sum += __expf(g_se[i] - m);
#pragma unroll
        for (int o = 16; o > 0; o >>= 1)
            sum += __shfl_xor_sync(0xffffffffu, sum, o);
        float eself = __expf(selfs - m);
        float inv = __fdividef(1.f, sum + eself);

        // Pass 3: weighted accumulate, 2 edges in flight (MLP)
        float cs = eself * inv;
        float4 hv = *(const float4*)(h + (size_t)n * HID + (lane << 2));
        float4 acc;
        acc.x = cs * hv.x; acc.y = cs * hv.y; acc.z = cs * hv.z; acc.w = cs * hv.w;

        int j = beg;
        for (; j + 2 <= end; j += 2) {
            float c0 = __expf(g_se[j] - m) * inv;
            float c1 = __expf(g_se[j + 1] - m) * inv;
            int s0 = g_csrc[j];
            int s1 = g_csrc[j + 1];
            float4 v0 = *(const float4*)(h + (size_t)s0 * HID + (lane << 2));
            float4 v1 = *(const float4*)(h + (size_t)s1 * HID + (lane << 2));
            acc.x += c0 * v0.x + c1 * v1.x;
            acc.y += c0 * v0.y + c1 * v1.y;
            acc.z += c0 * v0.z + c1 * v1.z;
            acc.w += c0 * v0.w + c1 * v1.w;
        }
        if (j < end) {
            float c = __expf(g_se[j] - m) * inv;
            int s = g_csrc[j];
            float4 v = *(const float4*)(h + (size_t)s * HID + (lane << 2));
            acc.x += c * v.x; acc.y += c * v.y; acc.z += c * v.z; acc.w += c * v.w;
        }

        float4 bv = *(const float4*)(bias + (lane << 2));
        outv.x = acc.x + bv.x; outv.y = acc.y + bv.y;
        outv.z = acc.z + bv.z; outv.w = acc.w + bv.w;
        *(float4*)(g_out + (size_t)n * HID + (lane << 2)) = outv;
    }

    // BN-stats: per-warp values into smem, block-reduce, 256 atomics/block
    int c0 = lane << 2;
    red[w][c0 + 0] = outv.x;
    red[w][c0 + 1] = outv.y;
    red[w][c0 + 2] = outv.z;
    red[w][c0 + 3] = outv.w;
    __syncthreads();

    int c = tid & (HID - 1);
    bool issq = tid >= HID;
    float a = 0.f;
#pragma unroll
    for (int w2 = 0; w2 < 8; w2++) {
        float v = red[w2][c];
        a += issq ? v * v : v;
    }
    atomicAdd(&g_stats[issq ? HID + c : c], a);
}

// ----------------------------------------------------------------------------
// Finalize BN: fold into scale+shift; re-zero stats for next layer/replay
// ----------------------------------------------------------------------------
__global__ void bnfinal_kernel(const float* __restrict__ gamma,
                               const float* __restrict__ beta)
{
    int c = threadIdx.x;                 // 128 threads
    float inv_n = 1.0f / (float)NNODES;
    float mean = g_stats[c] * inv_n;
    float var  = g_stats[HID + c] * inv_n - mean * mean;
    float sc = gamma[c] * rsqrtf(var + BN_EPS);
    g_bnsc[c] = sc;
    g_bnsh[c] = beta[c] - mean * sc;
    g_stats[c] = 0.f;
    g_stats[HID + c] = 0.f;
}

// ----------------------------------------------------------------------------
extern "C" void kernel_launch(void* const* d_in, const int* in_sizes, int n_in,
                              void* d_out, int out_size)
{
    const float* x    = (const float*)d_in[0];
    const int*   ei   = (const int*)d_in[1];     // int32 (JAX x64 disabled)
    const float* W1   = (const float*)d_in[2];
    const float* as1  = (const float*)d_in[3];
    const float* ad1  = (const float*)d_in[4];
    const float* b1   = (const float*)d_in[5];
    const float* g1   = (const float*)d_in[6];
    const float* be1  = (const float*)d_in[7];
    const float* W2   = (const float*)d_in[8];
    const float* as2  = (const float*)d_in[9];
    const float* ad2  = (const float*)d_in[10];
    const float* b2   = (const float*)d_in[11];
    const float* g2   = (const float*)d_in[12];
    const float* be2  = (const float*)d_in[13];
    const float* Wc   = (const float*)d_in[14];
    const float* bc   = (const float*)d_in[15];
    float*       out  = (float*)d_out;

    int E = in_sizes[1] / 2;
    if (E > EMAX) E = EMAX;
    const int* srcp = ei;
    const int* dstp = ei + E;

    float* d_h;
    cudaGetSymbolAddress((void**)&d_h, g_h);
    float* d_agg;
    cudaGetSymbolAddress((void**)&d_agg, g_out);
    uint2* d_Ap;
    cudaGetSymbolAddress((void**)&d_Ap, g_Ap);
    uint2* d_Bp;
    cudaGetSymbolAddress((void**)&d_Bp, g_Bp);

    // Dynamic smem sizes (3-stage pipeline + dot-reduction scratch)
    const int smem128 = (3 * 8 * 130 + 3 * 8 * 130) * (int)sizeof(uint2)
                      + 128 * 2 * 2 * (int)sizeof(float);
    const int smem64  = (3 * 8 * 130 + 3 * 8 * 66) * (int)sizeof(uint2)
                      + 128 * 2 * 2 * (int)sizeof(float);
    cudaFuncSetAttribute(
        mma_gemm_kernel<128, 128, 4, 2, false, false, true, 128>,
        cudaFuncAttributeMaxDynamicSharedMemorySize, smem128);
    cudaFuncSetAttribute(
        mma_gemm_kernel<128, 64, 4, 2, true, true, false, 128>,
        cudaFuncAttributeMaxDynamicSharedMemorySize, smem64);

    const int gemm_grid  = (NNODES + 127) / 128;
    const int node_grid  = (NNODES * 32 + 255) / 256;
    const int aprep_grid = (NNODES + 63) / 64;

    // ---- Prepack layer-1 operands; gemm1 at launch #4 for ncu window ----
    csr_zero_kernel<<<(NNODES + 255) / 256, 256>>>();
    aprep_kernel<false><<<aprep_grid, 256>>>(x);
    bprep_kernel<<<(64 * 128 + 255) / 256, 256>>>(W1, HID, HID, 128);
    mma_gemm_kernel<128, 128, 4, 2, false, false, true, 128>
        <<<gemm_grid, 256, smem128>>>(d_Ap, d_Bp, nullptr, as1, ad1,
                                      d_h, NNODES, HID, 128);
    // ---- CSR build (serial, proven) ----
    csr_count_kernel<<<(E + 255) / 256, 256>>>(dstp, E);
    csr_scan_block_kernel<<<NSCANBLK, SCAN_BLK>>>();
    csr_scan_tops_kernel<<<1, 128>>>(NSCANBLK, E);
    csr_addoff_kernel<<<NSCANBLK, SCAN_BLK>>>();
    csr_fill_kernel<<<(E + 255) / 256, 256>>>(srcp, dstp, E);

    // ---- Layer 1 attention + BN fold ----
    gat_node_kernel<<<node_grid, 256>>>(d_h, b1);
    bnfinal_kernel<<<1, 128>>>(g1, be1);

    // ---- Layer 2 ----
    aprep_kernel<true><<<aprep_grid, 256>>>(d_agg);
    bprep_kernel<<<(64 * 128 + 255) / 256, 256>>>(W2, HID, HID, 128);
    mma_gemm_kernel<128, 128, 4, 2, false, false, true, 128>
        <<<gemm_grid, 256, smem128>>>(d_Ap, d_Bp, nullptr, as2, ad2,
                                      d_h, NNODES, HID, 128);
    gat_node_kernel<<<node_grid, 256>>>(d_h, b2);
    bnfinal_kernel<<<1, 128>>>(g2, be2);

    // ---- Classifier: out = BN(out2) @ Wc + bc  (NC = NCLS — the R10 bug) ----
    aprep_kernel<true><<<aprep_grid, 256>>>(d_agg);
    bprep_kernel<<<(64 * 64 + 255) / 256, 256>>>(Wc, HID, NCLS, 64);
    mma_gemm_kernel<128, 64, 4, 2, true, true, false, 128>
        <<<gemm_grid, 256, smem64>>>(d_Ap, d_Bp, bc, nullptr, nullptr,
                                     out, NNODES, NCLS, 64);
}

// round 14
// speedup vs baseline: 1.0818x; 1.0818x over previous
#include <cuda_runtime.h>
#include <cuda_bf16.h>
#include <cstdint>

// Problem constants (fixed by the reference)
#define NNODES 100000
#define FDIM   128
#define HID    128
#define NCLS   40
#define EMAX   1600000
#define NEG_SLOPE 0.2f
#define BN_EPS 1e-5f

#define SCAN_BLK 1024
#define NSCANBLK ((NNODES + SCAN_BLK - 1) / SCAN_BLK)   // 98

// ----------------------------------------------------------------------------
// Device scratch (static globals — no runtime allocation allowed)
// ----------------------------------------------------------------------------
__device__ float g_h[NNODES * HID];      // linear output of current layer
__device__ float g_out[NNODES * HID];    // GAT aggregation output (pre-BN)
__device__ float g_as[NNODES];
__device__ float g_ad[NNODES];
__device__ float g_se[EMAX];             // cached per-slot edge scores
__device__ float g_stats[2 * HID];       // per-channel sum / sumsq
__device__ float g_bnsc[HID];            // folded BN scale (gamma * rstd)
__device__ float g_bnsh[HID];            // folded BN shift (beta - mean*scale)

// Prepacked bf16{hi,lo} operands, kp-major (kp = k/2 pair index)
__device__ uint2 g_Ap[64 * NNODES + 128];   // [kp][m], padded for tile overrun
__device__ uint2 g_Bp[64 * 128];            // [kp][n]

// CSR (dst -> list of src), rebuilt every launch (deterministic)
__device__ int g_deg[NNODES];
__device__ int g_fill[NNODES];           // running fill cursor (seeded = rowptr)
__device__ int g_rowptr[NNODES + 1];
__device__ int g_blocksum[128];
__device__ int g_csrc[EMAX];

// ----------------------------------------------------------------------------
__device__ __forceinline__ float lrelu(float x) {
    return x > 0.f ? x : NEG_SLOPE * x;
}

__device__ __forceinline__ unsigned bfpack(float lo, float hi) {
    __nv_bfloat162 p = __floats2bfloat162_rn(lo, hi);
    return *(unsigned*)&p;
}

__device__ __forceinline__ uint2 split2(float va, float vb) {
    float a0 = __bfloat162float(__float2bfloat16_rn(va));
    float b0 = __bfloat162float(__float2bfloat16_rn(vb));
    return make_uint2(bfpack(a0, b0), bfpack(va - a0, vb - b0));
}

__device__ __forceinline__ void mma_bf16(float d[4], const unsigned a[4],
                                         const unsigned b[2], const float c[4]) {
    asm volatile(
        "mma.sync.aligned.m16n8k16.row.col.f32.bf16.bf16.f32 "
        "{%0,%1,%2,%3}, {%4,%5,%6,%7}, {%8,%9}, {%10,%11,%12,%13};"
        : "=f"(d[0]), "=f"(d[1]), "=f"(d[2]), "=f"(d[3])
        : "r"(a[0]), "r"(a[1]), "r"(a[2]), "r"(a[3]),
          "r"(b[0]), "r"(b[1]),
          "f"(c[0]), "f"(c[1]), "f"(c[2]), "f"(c[3]));
}

__device__ __forceinline__ uint32_t smem_u32(const void* p) {
    return (uint32_t)__cvta_generic_to_shared(p);
}

// ----------------------------------------------------------------------------
// Prepack A: [m][k] float -> [kp][m] uint2 bf16{hi,lo}. Optional BN+ReLU.
// ----------------------------------------------------------------------------
template<bool BNA>
__global__ void aprep_kernel(const float* __restrict__ A)
{
    __shared__ uint2 s[64][65];
    int m0 = blockIdx.x * 64;
    for (int i = threadIdx.x; i < 64 * 64; i += 256) {
        int r = i >> 6, kp = i & 63;
        float2 v = make_float2(0.f, 0.f);
        if (m0 + r < NNODES)
            v = *(const float2*)(A + (size_t)(m0 + r) * HID + 2 * kp);
        if (BNA) {
            int c = 2 * kp;
            v.x = fmaxf(v.x * g_bnsc[c] + g_bnsh[c], 0.f);
            v.y = fmaxf(v.y * g_bnsc[c + 1] + g_bnsh[c + 1], 0.f);
        }
        s[r][kp] = split2(v.x, v.y);
    }
    __syncthreads();
    for (int i = threadIdx.x; i < 64 * 64; i += 256) {
        int kp = i >> 6, r = i & 63;
        if (m0 + r < NNODES)
            g_Ap[(size_t)kp * NNODES + m0 + r] = s[r][kp];
    }
}

// ----------------------------------------------------------------------------
// Prepack B: [k][n] float -> [kp][n] uint2 bf16{hi,lo}, n padded.
// ----------------------------------------------------------------------------
__global__ void bprep_kernel(const float* __restrict__ B, int K, int NC, int NPAD)
{
    int i = blockIdx.x * blockDim.x + threadIdx.x;
    if (i >= (K / 2) * NPAD) return;
    int kp = i / NPAD, n = i % NPAD;
    float be = 0.f, bo = 0.f;
    if (n < NC) {
        be = B[(size_t)(2 * kp) * NC + n];
        bo = B[(size_t)(2 * kp + 1) * NC + n];
    }
    g_Bp[i] = split2(be, bo);
}

// ----------------------------------------------------------------------------
// bf16x3 GEMM, 3-stage cp.async pipeline, FULLY UNROLLED (K compile-time).
// Optional fused alpha-dot epilogue (DOTS) writes g_as/g_ad.
// ----------------------------------------------------------------------------
template<int BM, int BN, int NWM, int NWN, bool BIAS, bool NGUARD, bool DOTS, int K>
__global__ void __launch_bounds__(NWM * NWN * 32, 2)
mma_gemm_kernel(const uint2* __restrict__ Ap, const uint2* __restrict__ Bp,
                const float* __restrict__ bias,
                const float* __restrict__ avs, const float* __restrict__ avd,
                float* __restrict__ C, int M, int NC, int NPAD)
{
    constexpr int THREADS = NWM * NWN * 32;
    constexpr int WM = BM / NWM;
    constexpr int WN = BN / NWN;
    constexpr int MT = WM / 16;
    constexpr int NT = WN / 8;
    constexpr int PAD = 2;
    constexpr int NITER = K / 16;

    extern __shared__ __align__(16) char dyn[];
    uint2 (*As)[8][BM + PAD] = (uint2(*)[8][BM + PAD])dyn;
    uint2 (*Bs)[8][BN + PAD] =
        (uint2(*)[8][BN + PAD])(dyn + 3 * 8 * (BM + PAD) * sizeof(uint2));
    float* sdot = (float*)(dyn + 3 * 8 * (BM + PAD) * sizeof(uint2)
                               + 3 * 8 * (BN + PAD) * sizeof(uint2));

    const int tid    = threadIdx.x;
    const int warpId = tid >> 5;
    const int lane   = tid & 31;
    const int warpM  = warpId % NWM;
    const int warpN  = warpId / NWM;
    const int t      = lane & 3;
    const int g      = lane >> 2;
    const int rowBase = blockIdx.x * BM;

#define ISSUE_STAGE(st, buf) do {                                              \
    int kpb = (st) * 8;                                                        \
    _Pragma("unroll")                                                          \
    for (int u = tid; u < (BM * 8) / 2; u += THREADS) {                        \
        int kpl = u / (BM / 2); int mu = u % (BM / 2);                         \
        const void* gsrc = Ap + (size_t)(kpb + kpl) * M + rowBase + mu * 2;    \
        uint32_t d = smem_u32(&As[buf][kpl][mu * 2]);                          \
        asm volatile("cp.async.cg.shared.global [%0], [%1], 16;"               \
                     :: "r"(d), "l"(gsrc));                                    \
    }                                                                          \
    _Pragma("unroll")                                                          \
    for (int u = tid; u < (BN * 8) / 2; u += THREADS) {                        \
        int kpl = u / (BN / 2); int nu = u % (BN / 2);                         \
        const void* gsrc = Bp + (size_t)(kpb + kpl) * NPAD + nu * 2;           \
        uint32_t d = smem_u32(&Bs[buf][kpl][nu * 2]);                          \
        asm volatile("cp.async.cg.shared.global [%0], [%1], 16;"               \
                     :: "r"(d), "l"(gsrc));                                    \
    }                                                                          \
    asm volatile("cp.async.commit_group;");                                    \
} while (0)

    float acc[MT][NT][4];
#pragma unroll
    for (int i = 0; i < MT; i++)
#pragma unroll
        for (int j = 0; j < NT; j++)
#pragma unroll
            for (int r = 0; r < 4; r++) acc[i][j][r] = 0.f;

    ISSUE_STAGE(0, 0);
    ISSUE_STAGE(1, 1);

#pragma unroll
    for (int it = 0; it < NITER; ++it) {
        if (it + 1 < NITER)
            asm volatile("cp.async.wait_group 1;");
        else
            asm volatile("cp.async.wait_group 0;");
        __syncthreads();
        if (it + 2 < NITER) ISSUE_STAGE(it + 2, (it + 2) % 3);

        const int cur = it % 3;
        unsigned a0[MT][4], a1[MT][4];
#pragma unroll
        for (int mt = 0; mt < MT; mt++) {
            int mr = warpM * WM + mt * 16;
            uint2 v0 = As[cur][t][mr + g];
            uint2 v1 = As[cur][t][mr + g + 8];
            uint2 v2 = As[cur][t + 4][mr + g];
            uint2 v3 = As[cur][t + 4][mr + g + 8];
            a0[mt][0] = v0.x; a1[mt][0] = v0.y;
            a0[mt][1] = v1.x; a1[mt][1] = v1.y;
            a0[mt][2] = v2.x; a1[mt][2] = v2.y;
            a0[mt][3] = v3.x; a1[mt][3] = v3.y;
        }
        unsigned b0[NT][2], b1[NT][2];
#pragma unroll
        for (int nt = 0; nt < NT; nt++) {
            int nc0 = warpN * WN + nt * 8;
            uint2 w0 = Bs[cur][t][nc0 + g];
            uint2 w1 = Bs[cur][t + 4][nc0 + g];
            b0[nt][0] = w0.x; b1[nt][0] = w0.y;
            b0[nt][1] = w1.x; b1[nt][1] = w1.y;
        }
#pragma unroll
        for (int mt = 0; mt < MT; mt++)
#pragma unroll
            for (int nt = 0; nt < NT; nt++) {
                mma_bf16(acc[mt][nt], a0[mt], b1[nt], acc[mt][nt]);
                mma_bf16(acc[mt][nt], a1[mt], b0[nt], acc[mt][nt]);
                mma_bf16(acc[mt][nt], a0[mt], b0[nt], acc[mt][nt]);
            }
    }
#undef ISSUE_STAGE

    // ---- C store ----
#pragma unroll
    for (int mt = 0; mt < MT; mt++) {
#pragma unroll
        for (int nt = 0; nt < NT; nt++) {
            int col = warpN * WN + nt * 8 + 2 * t;
            if (NGUARD && col >= NC) continue;
            float b0v = 0.f, b1v = 0.f;
            if (BIAS) { b0v = bias[col]; b1v = bias[col + 1]; }
            int row0 = rowBase + warpM * WM + mt * 16 + g;
            if (row0 < M) {
                float2 v = make_float2(acc[mt][nt][0] + b0v, acc[mt][nt][1] + b1v);
                *(float2*)(C + (size_t)row0 * NC + col) = v;
            }
            int row1 = row0 + 8;
            if (row1 < M) {
                float2 v = make_float2(acc[mt][nt][2] + b0v, acc[mt][nt][3] + b1v);
                *(float2*)(C + (size_t)row1 * NC + col) = v;
            }
        }
    }

    // ---- Fused alpha-dot epilogue ----
    if (DOTS) {
        float psA[MT], pdA[MT], psB[MT], pdB[MT];
#pragma unroll
        for (int mt = 0; mt < MT; mt++) {
            psA[mt] = 0.f; pdA[mt] = 0.f; psB[mt] = 0.f; pdB[mt] = 0.f;
        }
#pragma unroll
        for (int nt = 0; nt < NT; nt++) {
            int col = warpN * WN + nt * 8 + 2 * t;
            float s0 = avs[col], s1 = avs[col + 1];
            float d0 = avd[col], d1 = avd[col + 1];
#pragma unroll
            for (int mt = 0; mt < MT; mt++) {
                psA[mt] += acc[mt][nt][0] * s0 + acc[mt][nt][1] * s1;
                pdA[mt] += acc[mt][nt][0] * d0 + acc[mt][nt][1] * d1;
                psB[mt] += acc[mt][nt][2] * s0 + acc[mt][nt][3] * s1;
                pdB[mt] += acc[mt][nt][2] * d0 + acc[mt][nt][3] * d1;
            }
        }
#pragma unroll
        for (int o = 1; o <= 2; o <<= 1) {
#pragma unroll
            for (int mt = 0; mt < MT; mt++) {
                psA[mt] += __shfl_xor_sync(0xffffffffu, psA[mt], o);
                pdA[mt] += __shfl_xor_sync(0xffffffffu, pdA[mt], o);
                psB[mt] += __shfl_xor_sync(0xffffffffu, psB[mt], o);
                pdB[mt] += __shfl_xor_sync(0xffffffffu, pdB[mt], o);
            }
        }
        if (t == 0) {
#pragma unroll
            for (int mt = 0; mt < MT; mt++) {
                int rA = warpM * WM + mt * 16 + g;
                sdot[(rA * NWN + warpN) * 2 + 0] = psA[mt];
                sdot[(rA * NWN + warpN) * 2 + 1] = pdA[mt];
                sdot[((rA + 8) * NWN + warpN) * 2 + 0] = psB[mt];
                sdot[((rA + 8) * NWN + warpN) * 2 + 1] = pdB[mt];
            }
        }
        __syncthreads();
        for (int r = tid; r < BM; r += THREADS) {
            int grow = rowBase + r;
            if (grow < M) {
                float ss = 0.f, dd = 0.f;
#pragma unroll
                for (int wn = 0; wn < NWN; wn++) {
                    ss += sdot[(r * NWN + wn) * 2 + 0];
                    dd += sdot[(r * NWN + wn) * 2 + 1];
                }
                g_as[grow] = ss;
                g_ad[grow] = dd;
            }
        }
    }
}

// ----------------------------------------------------------------------------
// CSR build kernels (edge indices are int32)
// ----------------------------------------------------------------------------
__global__ void csr_zero_kernel()
{
    int i = blockIdx.x * blockDim.x + threadIdx.x;
    if (i < NNODES) g_deg[i] = 0;
    if (i < 2 * HID) g_stats[i] = 0.f;
}

__global__ void csr_count_kernel(const int* __restrict__ dstp, int E)
{
    int e = blockIdx.x * blockDim.x + threadIdx.x;
    if (e < E) atomicAdd(&g_deg[dstp[e]], 1);
}

__global__ void csr_scan_block_kernel()
{
    __shared__ int s[SCAN_BLK];
    int t = threadIdx.x;
    int i = blockIdx.x * SCAN_BLK + t;
    int v = (i < NNODES) ? g_deg[i] : 0;
    s[t] = v;
    __syncthreads();
#pragma unroll
    for (int off = 1; off < SCAN_BLK; off <<= 1) {
        int x = (t >= off) ? s[t - off] : 0;
        __syncthreads();
        s[t] += x;
        __syncthreads();
    }
    if (i < NNODES) g_rowptr[i] = s[t] - v;       // exclusive within block
    if (t == SCAN_BLK - 1) g_blocksum[blockIdx.x] = s[t];
}

__global__ void csr_scan_tops_kernel(int nblocks, int E)
{
    __shared__ int s[128];
    int t = threadIdx.x;                            // 128 threads
    int v = (t < nblocks) ? g_blocksum[t] : 0;
    s[t] = v;
    __syncthreads();
#pragma unroll
    for (int off = 1; off < 128; off <<= 1) {
        int x = (t >= off) ? s[t - off] : 0;
        __syncthreads();
        s[t] += x;
        __syncthreads();
    }
    g_blocksum[t] = s[t] - v;                       // exclusive block offsets
    if (t == 0) g_rowptr[NNODES] = E;
}

__global__ void csr_addoff_kernel()
{
    int i = blockIdx.x * SCAN_BLK + threadIdx.x;
    if (i < NNODES) {
        int r = g_rowptr[i] + g_blocksum[blockIdx.x];
        g_rowptr[i] = r;
        g_fill[i] = r;                              // seed fill cursor
    }
}

__global__ void csr_fill_kernel(const int* __restrict__ srcp,
                                const int* __restrict__ dstp, int E)
{
    int e = blockIdx.x * blockDim.x + threadIdx.x;
    if (e >= E) return;
    int p = atomicAdd(&g_fill[dstp[e]], 1);
    g_csrc[p] = srcp[e];
}

// ----------------------------------------------------------------------------
// Fused segment softmax + aggregation + bias + BN-stats.
// One warp per destination node; scores cached in g_se (coalesced reuse).
// Pass-3 is the R9 single-edge loop (the R13 x2 unroll regressed).
// ----------------------------------------------------------------------------
__global__ void gat_node_kernel(const float* __restrict__ h,
                                const float* __restrict__ bias)
{
    __shared__ float red[8][HID];

    const int tid  = threadIdx.x;
    const int w    = tid >> 5;
    const int lane = tid & 31;
    const int n    = (blockIdx.x * blockDim.x + tid) >> 5;

    float4 outv = make_float4(0.f, 0.f, 0.f, 0.f);

    if (n < NNODES) {
        const int beg = g_rowptr[n];
        const int end = g_rowptr[n + 1];
        const float adn = g_ad[n];
        const float selfs = lrelu(g_as[n] + adn);

        // Pass 1: gather scores once, cache, segment max
        float m = selfs;
        for (int i = beg + lane; i < end; i += 32) {
            float s = lrelu(g_as[g_csrc[i]] + adn);
            g_se[i] = s;
            m = fmaxf(m, s);
        }
#pragma unroll
        for (int o = 16; o > 0; o >>= 1)
            m = fmaxf(m, __shfl_xor_sync(0xffffffffu, m, o));
        __syncwarp();

        // Pass 2: exp-sum (coalesced reads of cached scores)
        float sum = 0.f;
        for (int i = beg + lane; i < end; i += 32)
            sum += __expf(g_se[i] - m);
#pragma unroll
        for (int o = 16; o > 0; o >>= 1)
            sum += __shfl_xor_sync(0xffffffffu, sum, o);
        float eself = __expf(selfs - m);
        float inv = __fdividef(1.f, sum + eself);

        // Pass 3: weighted accumulate (lanes own 4 channels each)
        float cs = eself * inv;
        float4 hv = *(const float4*)(h + (size_t)n * HID + (lane << 2));
        float4 acc;
        acc.x = cs * hv.x; acc.y = cs * hv.y; acc.z = cs * hv.z; acc.w = cs * hv.w;

        for (int j = beg; j < end; j++) {
            float c = __expf(g_se[j] - m) * inv;       // broadcast scalar load
            int s = g_csrc[j];
            float4 v = *(const float4*)(h + (size_t)s * HID + (lane << 2));
            acc.x += c * v.x; acc.y += c * v.y; acc.z += c * v.z; acc.w += c * v.w;
        }

        float4 bv = *(const float4*)(bias + (lane << 2));
        outv.x = acc.x + bv.x; outv.y = acc.y + bv.y;
        outv.z = acc.z + bv.z; outv.w = acc.w + bv.w;
        *(float4*)(g_out + (size_t)n * HID + (lane << 2)) = outv;
    }

    // BN-stats: per-warp values into smem, block-reduce, 256 atomics/block
    int c0 = lane << 2;
    red[w][c0 + 0] = outv.x;
    red[w][c0 + 1] = outv.y;
    red[w][c0 + 2] = outv.z;
    red[w][c0 + 3] = outv.w;
    __syncthreads();

    int c = tid & (HID - 1);
    bool issq = tid >= HID;
    float a = 0.f;
#pragma unroll
    for (int w2 = 0; w2 < 8; w2++) {
        float v = red[w2][c];
        a += issq ? v * v : v;
    }
    atomicAdd(&g_stats[issq ? HID + c : c], a);
}

// ----------------------------------------------------------------------------
// Finalize BN: fold into scale+shift; re-zero stats for next layer/replay
// ----------------------------------------------------------------------------
__global__ void bnfinal_kernel(const float* __restrict__ gamma,
                               const float* __restrict__ beta)
{
    int c = threadIdx.x;                 // 128 threads
    float inv_n = 1.0f / (float)NNODES;
    float mean = g_stats[c] * inv_n;
    float var  = g_stats[HID + c] * inv_n - mean * mean;
    float sc = gamma[c] * rsqrtf(var + BN_EPS);
    g_bnsc[c] = sc;
    g_bnsh[c] = beta[c] - mean * sc;
    g_stats[c] = 0.f;
    g_stats[HID + c] = 0.f;
}

// ----------------------------------------------------------------------------
extern "C" void kernel_launch(void* const* d_in, const int* in_sizes, int n_in,
                              void* d_out, int out_size)
{
    const float* x    = (const float*)d_in[0];
    const int*   ei   = (const int*)d_in[1];     // int32 (JAX x64 disabled)
    const float* W1   = (const float*)d_in[2];
    const float* as1  = (const float*)d_in[3];
    const float* ad1  = (const float*)d_in[4];
    const float* b1   = (const float*)d_in[5];
    const float* g1   = (const float*)d_in[6];
    const float* be1  = (const float*)d_in[7];
    const float* W2   = (const float*)d_in[8];
    const float* as2  = (const float*)d_in[9];
    const float* ad2  = (const float*)d_in[10];
    const float* b2   = (const float*)d_in[11];
    const float* g2   = (const float*)d_in[12];
    const float* be2  = (const float*)d_in[13];
    const float* Wc   = (const float*)d_in[14];
    const float* bc   = (const float*)d_in[15];
    float*       out  = (float*)d_out;

    int E = in_sizes[1] / 2;
    if (E > EMAX) E = EMAX;
    const int* srcp = ei;
    const int* dstp = ei + E;

    float* d_h;
    cudaGetSymbolAddress((void**)&d_h, g_h);
    float* d_agg;
    cudaGetSymbolAddress((void**)&d_agg, g_out);
    uint2* d_Ap;
    cudaGetSymbolAddress((void**)&d_Ap, g_Ap);
    uint2* d_Bp;
    cudaGetSymbolAddress((void**)&d_Bp, g_Bp);

    // Dynamic smem sizes (3-stage pipeline + dot-reduction scratch)
    const int smem128 = (3 * 8 * 130 + 3 * 8 * 130) * (int)sizeof(uint2)
                      + 128 * 2 * 2 * (int)sizeof(float);
    const int smem64  = (3 * 8 * 130 + 3 * 8 * 66) * (int)sizeof(uint2)
                      + 128 * 2 * 2 * (int)sizeof(float);
    cudaFuncSetAttribute(
        mma_gemm_kernel<128, 128, 4, 2, false, false, true, 128>,
        cudaFuncAttributeMaxDynamicSharedMemorySize, smem128);
    cudaFuncSetAttribute(
        mma_gemm_kernel<128, 64, 4, 2, true, true, false, 128>,
        cudaFuncAttributeMaxDynamicSharedMemorySize, smem64);

    // Lazy-created side stream + events (first call is the uncaptured
    // correctness run, so creation happens OUTSIDE graph capture; handles
    // are reused identically on the capture call -> deterministic work).
    static cudaStream_t s2 = nullptr;
    static cudaEvent_t  evFork = nullptr, evJoin = nullptr;
    if (!s2) {
        cudaStreamCreateWithFlags(&s2, cudaStreamNonBlocking);
        cudaEventCreateWithFlags(&evFork, cudaEventDisableTiming);
        cudaEventCreateWithFlags(&evJoin, cudaEventDisableTiming);
    }

    const int gemm_grid  = (NNODES + 127) / 128;
    const int node_grid  = (NNODES * 32 + 255) / 256;
    const int aprep_grid = (NNODES + 63) / 64;

    // ---- main: zero; fork CSR build to s2; prepack + gemm1 overlap it ----
    csr_zero_kernel<<<(NNODES + 255) / 256, 256>>>();
    cudaEventRecord(evFork, 0);
    cudaStreamWaitEvent(s2, evFork, 0);

    // s2: CSR build (independent of GEMM)
    csr_count_kernel<<<(E + 255) / 256, 256, 0, s2>>>(dstp, E);
    csr_scan_block_kernel<<<NSCANBLK, SCAN_BLK, 0, s2>>>();
    csr_scan_tops_kernel<<<1, 128, 0, s2>>>(NSCANBLK, E);
    csr_addoff_kernel<<<NSCANBLK, SCAN_BLK, 0, s2>>>();
    csr_fill_kernel<<<(E + 255) / 256, 256, 0, s2>>>(srcp, dstp, E);
    cudaEventRecord(evJoin, s2);

    // main: layer-1 prepack + GEMM (overlaps the CSR build)
    aprep_kernel<false><<<aprep_grid, 256>>>(x);
    bprep_kernel<<<(64 * 128 + 255) / 256, 256>>>(W1, HID, HID, 128);
    mma_gemm_kernel<128, 128, 4, 2, false, false, true, 128>
        <<<gemm_grid, 256, smem128>>>(d_Ap, d_Bp, nullptr, as1, ad1,
                                      d_h, NNODES, HID, 128);

    cudaStreamWaitEvent(0, evJoin, 0);   // join before attention

    // ---- Layer 1 attention + BN fold ----
    gat_node_kernel<<<node_grid, 256>>>(d_h, b1);
    bnfinal_kernel<<<1, 128>>>(g1, be1);

    // ---- Layer 2 ----
    aprep_kernel<true><<<aprep_grid, 256>>>(d_agg);
    bprep_kernel<<<(64 * 128 + 255) / 256, 256>>>(W2, HID, HID, 128);
    mma_gemm_kernel<128, 128, 4, 2, false, false, true, 128>
        <<<gemm_grid, 256, smem128>>>(d_Ap, d_Bp, nullptr, as2, ad2,
                                      d_h, NNODES, HID, 128);
    gat_node_kernel<<<node_grid, 256>>>(d_h, b2);
    bnfinal_kernel<<<1, 128>>>(g2, be2);

    // ---- Classifier: out = BN(out2) @ Wc + bc ----
    aprep_kernel<true><<<aprep_grid, 256>>>(d_agg);
    bprep_kernel<<<(64 * 64 + 255) / 256, 256>>>(Wc, HID, NCLS, 64);
    mma_gemm_kernel<128, 64, 4, 2, true, true, false, 128>
        <<<gemm_grid, 256, smem64>>>(d_Ap, d_Bp, bc, nullptr, nullptr,
                                     out, NNODES, NCLS, 64);
}

// round 17
// speedup vs baseline: 1.1703x; 1.0818x over previous
#include <cuda_runtime.h>
#include <cuda_bf16.h>
#include <cuda_fp16.h>
#include <cstdint>

// Problem constants (fixed by the reference)
#define NNODES 100000
#define FDIM   128
#define HID    128
#define NCLS   40
#define EMAX   1600000
#define NEG_SLOPE 0.2f
#define BN_EPS 1e-5f

#define SCAN_BLK 1024
#define NSCANBLK ((NNODES + SCAN_BLK - 1) / SCAN_BLK)   // 98

// ----------------------------------------------------------------------------
// Device scratch (static globals — no runtime allocation allowed)
// ----------------------------------------------------------------------------
__device__ unsigned g_h16[NNODES * 64 + 64];  // h rows as half2-packed (64 uints/row)
__device__ float g_out[NNODES * HID];    // GAT aggregation output (pre-BN)
__device__ float g_as[NNODES];
__device__ float g_ad[NNODES];
__device__ float g_se[EMAX];             // cached per-slot edge scores
__device__ float g_stats[2 * HID];       // per-channel sum / sumsq
__device__ float g_bnsc[HID];            // folded BN scale (gamma * rstd)
__device__ float g_bnsh[HID];            // folded BN shift (beta - mean*scale)

// Prepacked bf16{hi,lo} operands, kp-major (kp = k/2 pair index)
__device__ uint2 g_Ap[64 * NNODES + 128];   // [kp][m], padded for tile overrun
__device__ uint2 g_Bp[64 * 128];            // [kp][n]

// CSR (dst -> list of src), rebuilt every launch (deterministic)
__device__ int g_deg[NNODES];
__device__ int g_fill[NNODES];           // running fill cursor (seeded = rowptr)
__device__ int g_rowptr[NNODES + 1];
__device__ int g_blocksum[128];
__device__ int g_csrc[EMAX];

// ----------------------------------------------------------------------------
__device__ __forceinline__ float lrelu(float x) {
    return x > 0.f ? x : NEG_SLOPE * x;
}

__device__ __forceinline__ unsigned bfpack(float lo, float hi) {
    __nv_bfloat162 p = __floats2bfloat162_rn(lo, hi);
    return *(unsigned*)&p;
}

__device__ __forceinline__ uint2 split2(float va, float vb) {
    float a0 = __bfloat162float(__float2bfloat16_rn(va));
    float b0 = __bfloat162float(__float2bfloat16_rn(vb));
    return make_uint2(bfpack(a0, b0), bfpack(va - a0, vb - b0));
}

__device__ __forceinline__ void mma_bf16(float d[4], const unsigned a[4],
                                         const unsigned b[2], const float c[4]) {
    asm volatile(
        "mma.sync.aligned.m16n8k16.row.col.f32.bf16.bf16.f32 "
        "{%0,%1,%2,%3}, {%4,%5,%6,%7}, {%8,%9}, {%10,%11,%12,%13};"
        : "=f"(d[0]), "=f"(d[1]), "=f"(d[2]), "=f"(d[3])
        : "r"(a[0]), "r"(a[1]), "r"(a[2]), "r"(a[3]),
          "r"(b[0]), "r"(b[1]),
          "f"(c[0]), "f"(c[1]), "f"(c[2]), "f"(c[3]));
}

__device__ __forceinline__ uint32_t smem_u32(const void* p) {
    return (uint32_t)__cvta_generic_to_shared(p);
}

// ----------------------------------------------------------------------------
// Prepack A: [m][k] float -> [kp][m] uint2 bf16{hi,lo}. Optional BN+ReLU.
// ----------------------------------------------------------------------------
template<bool BNA>
__global__ void aprep_kernel(const float* __restrict__ A)
{
    __shared__ uint2 s[64][65];
    int m0 = blockIdx.x * 64;
    for (int i = threadIdx.x; i < 64 * 64; i += 256) {
        int r = i >> 6, kp = i & 63;
        float2 v = make_float2(0.f, 0.f);
        if (m0 + r < NNODES)
            v = *(const float2*)(A + (size_t)(m0 + r) * HID + 2 * kp);
        if (BNA) {
            int c = 2 * kp;
            v.x = fmaxf(v.x * g_bnsc[c] + g_bnsh[c], 0.f);
            v.y = fmaxf(v.y * g_bnsc[c + 1] + g_bnsh[c + 1], 0.f);
        }
        s[r][kp] = split2(v.x, v.y);
    }
    __syncthreads();
    for (int i = threadIdx.x; i < 64 * 64; i += 256) {
        int kp = i >> 6, r = i & 63;
        if (m0 + r < NNODES)
            g_Ap[(size_t)kp * NNODES + m0 + r] = s[r][kp];
    }
}

// ----------------------------------------------------------------------------
// Prepack B: [k][n] float -> [kp][n] uint2 bf16{hi,lo}, n padded.
// ----------------------------------------------------------------------------
__global__ void bprep_kernel(const float* __restrict__ B, int K, int NC, int NPAD)
{
    int i = blockIdx.x * blockDim.x + threadIdx.x;
    if (i >= (K / 2) * NPAD) return;
    int kp = i / NPAD, n = i % NPAD;
    float be = 0.f, bo = 0.f;
    if (n < NC) {
        be = B[(size_t)(2 * kp) * NC + n];
        bo = B[(size_t)(2 * kp + 1) * NC + n];
    }
    g_Bp[i] = split2(be, bo);
}

// ----------------------------------------------------------------------------
// bf16x3 GEMM, 3-stage cp.async pipeline, FULLY UNROLLED (K compile-time).
// H16: C is half2-packed (unsigned*, NC/2 uints per row).
// DOTS: fused alpha-dot epilogue writes g_as/g_ad.
// ----------------------------------------------------------------------------
template<int BM, int BN, int NWM, int NWN, bool BIAS, bool NGUARD, bool DOTS,
         bool H16, int K>
__global__ void __launch_bounds__(NWM * NWN * 32, 2)
mma_gemm_kernel(const uint2* __restrict__ Ap, const uint2* __restrict__ Bp,
                const float* __restrict__ bias,
                const float* __restrict__ avs, const float* __restrict__ avd,
                void* __restrict__ Cout, int M, int NC, int NPAD)
{
    constexpr int THREADS = NWM * NWN * 32;
    constexpr int WM = BM / NWM;
    constexpr int WN = BN / NWN;
    constexpr int MT = WM / 16;
    constexpr int NT = WN / 8;
    constexpr int PAD = 2;
    constexpr int NITER = K / 16;

    extern __shared__ __align__(16) char dyn[];
    uint2 (*As)[8][BM + PAD] = (uint2(*)[8][BM + PAD])dyn;
    uint2 (*Bs)[8][BN + PAD] =
        (uint2(*)[8][BN + PAD])(dyn + 3 * 8 * (BM + PAD) * sizeof(uint2));
    float* sdot = (float*)(dyn + 3 * 8 * (BM + PAD) * sizeof(uint2)
                               + 3 * 8 * (BN + PAD) * sizeof(uint2));

    const int tid    = threadIdx.x;
    const int warpId = tid >> 5;
    const int lane   = tid & 31;
    const int warpM  = warpId % NWM;
    const int warpN  = warpId / NWM;
    const int t      = lane & 3;
    const int g      = lane >> 2;
    const int rowBase = blockIdx.x * BM;

#define ISSUE_STAGE(st, buf) do {                                              \
    int kpb = (st) * 8;                                                        \
    _Pragma("unroll")                                                          \
    for (int u = tid; u < (BM * 8) / 2; u += THREADS) {                        \
        int kpl = u / (BM / 2); int mu = u % (BM / 2);                         \
        const void* gsrc = Ap + (size_t)(kpb + kpl) * M + rowBase + mu * 2;    \
        uint32_t d = smem_u32(&As[buf][kpl][mu * 2]);                          \
        asm volatile("cp.async.cg.shared.global [%0], [%1], 16;"               \
                     :: "r"(d), "l"(gsrc));                                    \
    }                                                                          \
    _Pragma("unroll")                                                          \
    for (int u = tid; u < (BN * 8) / 2; u += THREADS) {                        \
        int kpl = u / (BN / 2); int nu = u % (BN / 2);                         \
        const void* gsrc = Bp + (size_t)(kpb + kpl) * NPAD + nu * 2;           \
        uint32_t d = smem_u32(&Bs[buf][kpl][nu * 2]);                          \
        asm volatile("cp.async.cg.shared.global [%0], [%1], 16;"               \
                     :: "r"(d), "l"(gsrc));                                    \
    }                                                                          \
    asm volatile("cp.async.commit_group;");                                    \
} while (0)

    float acc[MT][NT][4];
#pragma unroll
    for (int i = 0; i < MT; i++)
#pragma unroll
        for (int j = 0; j < NT; j++)
#pragma unroll
            for (int r = 0; r < 4; r++) acc[i][j][r] = 0.f;

    ISSUE_STAGE(0, 0);
    ISSUE_STAGE(1, 1);

#pragma unroll
    for (int it = 0; it < NITER; ++it) {
        if (it + 1 < NITER)
            asm volatile("cp.async.wait_group 1;");
        else
            asm volatile("cp.async.wait_group 0;");
        __syncthreads();
        if (it + 2 < NITER) ISSUE_STAGE(it + 2, (it + 2) % 3);

        const int cur = it % 3;
        unsigned a0[MT][4], a1[MT][4];
#pragma unroll
        for (int mt = 0; mt < MT; mt++) {
            int mr = warpM * WM + mt * 16;
            uint2 v0 = As[cur][t][mr + g];
            uint2 v1 = As[cur][t][mr + g + 8];
            uint2 v2 = As[cur][t + 4][mr + g];
            uint2 v3 = As[cur][t + 4][mr + g + 8];
            a0[mt][0] = v0.x; a1[mt][0] = v0.y;
            a0[mt][1] = v1.x; a1[mt][1] = v1.y;
            a0[mt][2] = v2.x; a1[mt][2] = v2.y;
            a0[mt][3] = v3.x; a1[mt][3] = v3.y;
        }
        unsigned b0[NT][2], b1[NT][2];
#pragma unroll
        for (int nt = 0; nt < NT; nt++) {
            int nc0 = warpN * WN + nt * 8;
            uint2 w0 = Bs[cur][t][nc0 + g];
            uint2 w1 = Bs[cur][t + 4][nc0 + g];
            b0[nt][0] = w0.x; b1[nt][0] = w0.y;
            b0[nt][1] = w1.x; b1[nt][1] = w1.y;
        }
#pragma unroll
        for (int mt = 0; mt < MT; mt++)
#pragma unroll
            for (int nt = 0; nt < NT; nt++) {
                mma_bf16(acc[mt][nt], a0[mt], b1[nt], acc[mt][nt]);
                mma_bf16(acc[mt][nt], a1[mt], b0[nt], acc[mt][nt]);
                mma_bf16(acc[mt][nt], a0[mt], b0[nt], acc[mt][nt]);
            }
    }
#undef ISSUE_STAGE

    // ---- C store (fp32 or half2-packed) ----
#pragma unroll
    for (int mt = 0; mt < MT; mt++) {
#pragma unroll
        for (int nt = 0; nt < NT; nt++) {
            int col = warpN * WN + nt * 8 + 2 * t;
            if (NGUARD && col >= NC) continue;
            float b0v = 0.f, b1v = 0.f;
            if (BIAS) { b0v = bias[col]; b1v = bias[col + 1]; }
            int row0 = rowBase + warpM * WM + mt * 16 + g;
            int row1 = row0 + 8;
            if (H16) {
                unsigned* C16 = (unsigned*)Cout;
                if (row0 < M) {
                    __half2 h = __floats2half2_rn(acc[mt][nt][0] + b0v,
                                                  acc[mt][nt][1] + b1v);
                    C16[(size_t)row0 * (NC / 2) + (col >> 1)] = *(unsigned*)&h;
                }
                if (row1 < M) {
                    __half2 h = __floats2half2_rn(acc[mt][nt][2] + b0v,
                                                  acc[mt][nt][3] + b1v);
                    C16[(size_t)row1 * (NC / 2) + (col >> 1)] = *(unsigned*)&h;
                }
            } else {
                float* C = (float*)Cout;
                if (row0 < M) {
                    float2 v = make_float2(acc[mt][nt][0] + b0v,
                                           acc[mt][nt][1] + b1v);
                    *(float2*)(C + (size_t)row0 * NC + col) = v;
                }
                if (row1 < M) {
                    float2 v = make_float2(acc[mt][nt][2] + b0v,
                                           acc[mt][nt][3] + b1v);
                    *(float2*)(C + (size_t)row1 * NC + col) = v;
                }
            }
        }
    }

    // ---- Fused alpha-dot epilogue ----
    if (DOTS) {
        float psA[MT], pdA[MT], psB[MT], pdB[MT];
#pragma unroll
        for (int mt = 0; mt < MT; mt++) {
            psA[mt] = 0.f; pdA[mt] = 0.f; psB[mt] = 0.f; pdB[mt] = 0.f;
        }
#pragma unroll
        for (int nt = 0; nt < NT; nt++) {
            int col = warpN * WN + nt * 8 + 2 * t;
            float s0 = avs[col], s1 = avs[col + 1];
            float d0 = avd[col], d1 = avd[col + 1];
#pragma unroll
            for (int mt = 0; mt < MT; mt++) {
                psA[mt] += acc[mt][nt][0] * s0 + acc[mt][nt][1] * s1;
                pdA[mt] += acc[mt][nt][0] * d0 + acc[mt][nt][1] * d1;
                psB[mt] += acc[mt][nt][2] * s0 + acc[mt][nt][3] * s1;
                pdB[mt] += acc[mt][nt][2] * d0 + acc[mt][nt][3] * d1;
            }
        }
#pragma unroll
        for (int o = 1; o <= 2; o <<= 1) {
#pragma unroll
            for (int mt = 0; mt < MT; mt++) {
                psA[mt] += __shfl_xor_sync(0xffffffffu, psA[mt], o);
                pdA[mt] += __shfl_xor_sync(0xffffffffu, pdA[mt], o);
                psB[mt] += __shfl_xor_sync(0xffffffffu, psB[mt], o);
                pdB[mt] += __shfl_xor_sync(0xffffffffu, pdB[mt], o);
            }
        }
        if (t == 0) {
#pragma unroll
            for (int mt = 0; mt < MT; mt++) {
                int rA = warpM * WM + mt * 16 + g;
                sdot[(rA * NWN + warpN) * 2 + 0] = psA[mt];
                sdot[(rA * NWN + warpN) * 2 + 1] = pdA[mt];
                sdot[((rA + 8) * NWN + warpN) * 2 + 0] = psB[mt];
                sdot[((rA + 8) * NWN + warpN) * 2 + 1] = pdB[mt];
            }
        }
        __syncthreads();
        for (int r = tid; r < BM; r += THREADS) {
            int grow = rowBase + r;
            if (grow < M) {
                float ss = 0.f, dd = 0.f;
#pragma unroll
                for (int wn = 0; wn < NWN; wn++) {
                    ss += sdot[(r * NWN + wn) * 2 + 0];
                    dd += sdot[(r * NWN + wn) * 2 + 1];
                }
                g_as[grow] = ss;
                g_ad[grow] = dd;
            }
        }
    }
}

// ----------------------------------------------------------------------------
// CSR build kernels (edge indices are int32)
// ----------------------------------------------------------------------------
__global__ void csr_zero_kernel()
{
    int i = blockIdx.x * blockDim.x + threadIdx.x;
    if (i < NNODES) g_deg[i] = 0;
    if (i < 2 * HID) g_stats[i] = 0.f;
}

__global__ void csr_count_kernel(const int* __restrict__ dstp, int E)
{
    int e = blockIdx.x * blockDim.x + threadIdx.x;
    if (e < E) atomicAdd(&g_deg[dstp[e]], 1);
}

__global__ void csr_scan_block_kernel()
{
    __shared__ int s[SCAN_BLK];
    int t = threadIdx.x;
    int i = blockIdx.x * SCAN_BLK + t;
    int v = (i < NNODES) ? g_deg[i] : 0;
    s[t] = v;
    __syncthreads();
#pragma unroll
    for (int off = 1; off < SCAN_BLK; off <<= 1) {
        int x = (t >= off) ? s[t - off] : 0;
        __syncthreads();
        s[t] += x;
        __syncthreads();
    }
    if (i < NNODES) g_rowptr[i] = s[t] - v;       // exclusive within block
    if (t == SCAN_BLK - 1) g_blocksum[blockIdx.x] = s[t];
}

__global__ void csr_scan_tops_kernel(int nblocks, int E)
{
    __shared__ int s[128];
    int t = threadIdx.x;                            // 128 threads
    int v = (t < nblocks) ? g_blocksum[t] : 0;
    s[t] = v;
    __syncthreads();
#pragma unroll
    for (int off = 1; off < 128; off <<= 1) {
        int x = (t >= off) ? s[t - off] : 0;
        __syncthreads();
        s[t] += x;
        __syncthreads();
    }
    g_blocksum[t] = s[t] - v;                       // exclusive block offsets
    if (t == 0) g_rowptr[NNODES] = E;
}

__global__ void csr_addoff_kernel()
{
    int i = blockIdx.x * SCAN_BLK + threadIdx.x;
    if (i < NNODES) {
        int r = g_rowptr[i] + g_blocksum[blockIdx.x];
        g_rowptr[i] = r;
        g_fill[i] = r;                              // seed fill cursor
    }
}

__global__ void csr_fill_kernel(const int* __restrict__ srcp,
                                const int* __restrict__ dstp, int E)
{
    int e = blockIdx.x * blockDim.x + threadIdx.x;
    if (e >= E) return;
    int p = atomicAdd(&g_fill[dstp[e]], 1);
    g_csrc[p] = srcp[e];
}

// ----------------------------------------------------------------------------
// Fused segment softmax + aggregation + bias + BN-stats.
// One warp per destination node; h rows gathered as packed fp16 (256 B/row).
// ----------------------------------------------------------------------------
__global__ void gat_node_kernel(const float* __restrict__ bias)
{
    __shared__ float red[8][HID];

    const int tid  = threadIdx.x;
    const int w    = tid >> 5;
    const int lane = tid & 31;
    const int n    = (blockIdx.x * blockDim.x + tid) >> 5;

    float4 outv = make_float4(0.f, 0.f, 0.f, 0.f);

    if (n < NNODES) {
        const int beg = g_rowptr[n];
        const int end = g_rowptr[n + 1];
        const float adn = g_ad[n];
        const float selfs = lrelu(g_as[n] + adn);

        // Pass 1: gather scores once, cache, segment max
        float m = selfs;
        for (int i = beg + lane; i < end; i += 32) {
            float s = lrelu(g_as[g_csrc[i]] + adn);
            g_se[i] = s;
            m = fmaxf(m, s);
        }
#pragma unroll
        for (int o = 16; o > 0; o >>= 1)
            m = fmaxf(m, __shfl_xor_sync(0xffffffffu, m, o));
        __syncwarp();

        // Pass 2: exp-sum (coalesced reads of cached scores)
        float sum = 0.f;
        for (int i = beg + lane; i < end; i += 32)
            sum += __expf(g_se[i] - m);
#pragma unroll
        for (int o = 16; o > 0; o >>= 1)
            sum += __shfl_xor_sync(0xffffffffu, sum, o);
        float eself = __expf(selfs - m);
        float inv = __fdividef(1.f, sum + eself);

        // Pass 3: weighted accumulate over fp16 rows (lane owns 4 channels)
        float cs = eself * inv;
        uint2 hu = *(const uint2*)(g_h16 + (size_t)n * 64 + (lane << 1));
        float2 h0 = __half22float2(*(__half2*)&hu.x);
        float2 h1 = __half22float2(*(__half2*)&hu.y);
        float4 acc;
        acc.x = cs * h0.x; acc.y = cs * h0.y; acc.z = cs * h1.x; acc.w = cs * h1.y;

        for (int j = beg; j < end; j++) {
            float c = __expf(g_se[j] - m) * inv;       // broadcast scalar load
            int s = g_csrc[j];
            uint2 vu = *(const uint2*)(g_h16 + (size_t)s * 64 + (lane << 1));
            float2 v0 = __half22float2(*(__half2*)&vu.x);
            float2 v1 = __half22float2(*(__half2*)&vu.y);
            acc.x += c * v0.x; acc.y += c * v0.y;
            acc.z += c * v1.x; acc.w += c * v1.y;
        }

        float4 bv = *(const float4*)(bias + (lane << 2));
        outv.x = acc.x + bv.x; outv.y = acc.y + bv.y;
        outv.z = acc.z + bv.z; outv.w = acc.w + bv.w;
        *(float4*)(g_out + (size_t)n * HID + (lane << 2)) = outv;
    }

    // BN-stats: per-warp values into smem, block-reduce, 256 atomics/block
    int c0 = lane << 2;
    red[w][c0 + 0] = outv.x;
    red[w][c0 + 1] = outv.y;
    red[w][c0 + 2] = outv.z;
    red[w][c0 + 3] = outv.w;
    __syncthreads();

    int c = tid & (HID - 1);
    bool issq = tid >= HID;
    float a = 0.f;
#pragma unroll
    for (int w2 = 0; w2 < 8; w2++) {
        float v = red[w2][c];
        a += issq ? v * v : v;
    }
    atomicAdd(&g_stats[issq ? HID + c : c], a);
}

// ----------------------------------------------------------------------------
// Finalize BN: fold into scale+shift; re-zero stats for next layer/replay
// ----------------------------------------------------------------------------
__global__ void bnfinal_kernel(const float* __restrict__ gamma,
                               const float* __restrict__ beta)
{
    int c = threadIdx.x;                 // 128 threads
    float inv_n = 1.0f / (float)NNODES;
    float mean = g_stats[c] * inv_n;
    float var  = g_stats[HID + c] * inv_n - mean * mean;
    float sc = gamma[c] * rsqrtf(var + BN_EPS);
    g_bnsc[c] = sc;
    g_bnsh[c] = beta[c] - mean * sc;
    g_stats[c] = 0.f;
    g_stats[HID + c] = 0.f;
}

// ----------------------------------------------------------------------------
extern "C" void kernel_launch(void* const* d_in, const int* in_sizes, int n_in,
                              void* d_out, int out_size)
{
    const float* x    = (const float*)d_in[0];
    const int*   ei   = (const int*)d_in[1];     // int32 (JAX x64 disabled)
    const float* W1   = (const float*)d_in[2];
    const float* as1  = (const float*)d_in[3];
    const float* ad1  = (const float*)d_in[4];
    const float* b1   = (const float*)d_in[5];
    const float* g1   = (const float*)d_in[6];
    const float* be1  = (const float*)d_in[7];
    const float* W2   = (const float*)d_in[8];
    const float* as2  = (const float*)d_in[9];
    const float* ad2  = (const float*)d_in[10];
    const float* b2   = (const float*)d_in[11];
    const float* g2   = (const float*)d_in[12];
    const float* be2  = (const float*)d_in[13];
    const float* Wc   = (const float*)d_in[14];
    const float* bc   = (const float*)d_in[15];
    float*       out  = (float*)d_out;

    int E = in_sizes[1] / 2;
    if (E > EMAX) E = EMAX;
    const int* srcp = ei;
    const int* dstp = ei + E;

    unsigned* d_h16;
    cudaGetSymbolAddress((void**)&d_h16, g_h16);
    float* d_agg;
    cudaGetSymbolAddress((void**)&d_agg, g_out);
    uint2* d_Ap;
    cudaGetSymbolAddress((void**)&d_Ap, g_Ap);
    uint2* d_Bp;
    cudaGetSymbolAddress((void**)&d_Bp, g_Bp);

    // Dynamic smem sizes (3-stage pipeline + dot-reduction scratch)
    const int smem128 = (3 * 8 * 130 + 3 * 8 * 130) * (int)sizeof(uint2)
                      + 128 * 2 * 2 * (int)sizeof(float);
    const int smem64  = (3 * 8 * 130 + 3 * 8 * 66) * (int)sizeof(uint2)
                      + 128 * 2 * 2 * (int)sizeof(float);
    cudaFuncSetAttribute(
        mma_gemm_kernel<128, 128, 4, 2, false, false, true, true, 128>,
        cudaFuncAttributeMaxDynamicSharedMemorySize, smem128);
    cudaFuncSetAttribute(
        mma_gemm_kernel<128, 64, 4, 2, true, true, false, false, 128>,
        cudaFuncAttributeMaxDynamicSharedMemorySize, smem64);

    // Lazy-created side stream + events (created on the uncaptured
    // correctness run; reused identically during capture).
    static cudaStream_t s2 = nullptr;
    static cudaEvent_t  evFork = nullptr, evJoin = nullptr;
    if (!s2) {
        cudaStreamCreateWithFlags(&s2, cudaStreamNonBlocking);
        cudaEventCreateWithFlags(&evFork, cudaEventDisableTiming);
        cudaEventCreateWithFlags(&evJoin, cudaEventDisableTiming);
    }

    const int gemm_grid  = (NNODES + 127) / 128;
    const int node_grid  = (NNODES * 32 + 255) / 256;
    const int aprep_grid = (NNODES + 63) / 64;

    // ---- main: zero; fork CSR build to s2; prepack + gemm1 overlap it ----
    csr_zero_kernel<<<(NNODES + 255) / 256, 256>>>();
    cudaEventRecord(evFork, 0);
    cudaStreamWaitEvent(s2, evFork, 0);

    // s2: CSR build (independent of GEMM)
    csr_count_kernel<<<(E + 255) / 256, 256, 0, s2>>>(dstp, E);
    csr_scan_block_kernel<<<NSCANBLK, SCAN_BLK, 0, s2>>>();
    csr_scan_tops_kernel<<<1, 128, 0, s2>>>(NSCANBLK, E);
    csr_addoff_kernel<<<NSCANBLK, SCAN_BLK, 0, s2>>>();
    csr_fill_kernel<<<(E + 255) / 256, 256, 0, s2>>>(srcp, dstp, E);
    cudaEventRecord(evJoin, s2);

    // main: layer-1 prepack + GEMM (overlaps the CSR build)
    aprep_kernel<false><<<aprep_grid, 256>>>(x);
    bprep_kernel<<<(64 * 128 + 255) / 256, 256>>>(W1, HID, HID, 128);
    mma_gemm_kernel<128, 128, 4, 2, false, false, true, true, 128>
        <<<gemm_grid, 256, smem128>>>(d_Ap, d_Bp, nullptr, as1, ad1,
                                      d_h16, NNODES, HID, 128);

    cudaStreamWaitEvent(0, evJoin, 0);   // join before attention

    // ---- Layer 1 attention + BN fold ----
    gat_node_kernel<<<node_grid, 256>>>(b1);
    bnfinal_kernel<<<1, 128>>>(g1, be1);

    // ---- Layer 2 ----
    aprep_kernel<true><<<aprep_grid, 256>>>(d_agg);
    bprep_kernel<<<(64 * 128 + 255) / 256, 256>>>(W2, HID, HID, 128);
    mma_gemm_kernel<128, 128, 4, 2, false, false, true, true, 128>
        <<<gemm_grid, 256, smem128>>>(d_Ap, d_Bp, nullptr, as2, ad2,
                                      d_h16, NNODES, HID, 128);
    gat_node_kernel<<<node_grid, 256>>>(b2);
    bnfinal_kernel<<<1, 128>>>(g2, be2);

    // ---- Classifier: out = BN(out2) @ Wc + bc (fp32 output) ----
    aprep_kernel<true><<<aprep_grid, 256>>>(d_agg);
    bprep_kernel<<<(64 * 64 + 255) / 256, 256>>>(Wc, HID, NCLS, 64);
    mma_gemm_kernel<128, 64, 4, 2, true, true, false, false, 128>
        <<<gemm_grid, 256, smem64>>>(d_Ap, d_Bp, bc, nullptr, nullptr,
                                     out, NNODES, NCLS, 64);
}